// round 16
// baseline (speedup 1.0000x reference)
#include <cuda_runtime.h>
#include <cuda_fp16.h>
#include <mma.h>
#include <cstdint>
#include <cstddef>

using namespace nvcuda;

#define NN 10000
#define EE 160000
#define PAIRS 20000
#define NODE_FLOATS 512
#define NTILES 2500

struct __align__(8) EdgeP { int src; float w; };

// ---------------- device scratch ----------------
__device__ float  d_Tx1[(size_t)PAIRS * NODE_FLOATS];
__device__ __half d_Tx1h[(size_t)PAIRS * NODE_FLOATS];
__device__ float  d_P2 [(size_t)PAIRS * NODE_FLOATS];
__device__ int   d_degc[NN];     // zero at launch entry (reset by scan_kernel)
__device__ float d_dinv[NN];
__device__ int   d_cnt[NN];      // zero at launch entry (reset by scan_kernel)
__device__ int   d_ptr[NN + 1];
__device__ int   d_wr[NN];
__device__ EdgeP d_epk[EE];

// ---------------- CSR build ----------------
__global__ void count_kernel(const int* __restrict__ row, const int* __restrict__ col) {
    int e = blockIdx.x * blockDim.x + threadIdx.x;
    if (e < EE) {
        atomicAdd(&d_degc[row[e]], 1);
        atomicAdd(&d_cnt[col[e]], 1);
    }
}

// dinv + chunked scan (coalesced d_ptr/d_wr writes) + reset counts for next replay
__global__ void scan_kernel() {
    __shared__ int buf[NN];       // 40KB
    __shared__ int wsum[32];
    __shared__ int carry;
    int tid = threadIdx.x, lane = tid & 31, wid = tid >> 5;
    if (tid == 0) carry = 0;
    for (int i = tid; i < NN; i += 1024) {
        int d = d_degc[i];
        d_dinv[i] = (d > 0) ? rsqrtf((float)d) : 0.f;
        buf[i] = d_cnt[i];
        d_degc[i] = 0;            // restore zero-invariant for next graph replay
        d_cnt[i]  = 0;
    }
    __syncthreads();
    for (int base = 0; base < NN; base += 1024) {
        int i = base + tid;
        int v = (i < NN) ? buf[i] : 0;
        int s = v;
#pragma unroll
        for (int off = 1; off < 32; off <<= 1) {
            int t = __shfl_up_sync(0xffffffffu, s, off);
            if (lane >= off) s += t;
        }
        if (lane == 31) wsum[wid] = s;
        __syncthreads();
        if (wid == 0) {
            int ws = wsum[lane];
#pragma unroll
            for (int off = 1; off < 32; off <<= 1) {
                int t = __shfl_up_sync(0xffffffffu, ws, off);
                if (lane >= off) ws += t;
            }
            wsum[lane] = ws;
        }
        __syncthreads();
        int incl = s + ((wid > 0) ? wsum[wid - 1] : 0);
        int c0 = carry;
        if (i < NN) { int ex = c0 + incl - v; d_ptr[i] = ex; d_wr[i] = ex; }
        __syncthreads();
        if (tid == 1023) carry = c0 + incl;
        __syncthreads();
    }
    if (tid == 0) d_ptr[NN] = carry;
}

__global__ void fill_kernel(const int* __restrict__ row, const int* __restrict__ col) {
    int e = blockIdx.x * blockDim.x + threadIdx.x;
    if (e < EE) {
        int r = row[e], c = col[e];
        float wv = -(d_dinv[r] * d_dinv[c]);
        int pos = atomicAdd(&d_wr[c], 1);
        EdgeP ep; ep.src = r; ep.w = wv;
        d_epk[pos] = ep;
    }
}

// ---------------- prop1: smem-staged edges, 4-way MLP fp32 gather; writes Tx1 fp32 + f16 ----------------
__global__ __launch_bounds__(256) void prop1_kernel(const float* __restrict__ z,
                                                    float* __restrict__ outp,
                                                    __half* __restrict__ outh) {
    __shared__ EdgeP se[256];
    int n = blockIdx.x;
    int tid = threadIdx.x;
    int b = tid >> 7;
    int q = tid & 127;
    const float4* zb = reinterpret_cast<const float4*>(z) + b * (NN * 128) + q;
    float4 acc = make_float4(0.f, 0.f, 0.f, 0.f);
    int s = d_ptr[n], e = d_ptr[n + 1];
    for (int base = s; base < e; base += 256) {
        int cnt = min(256, e - base);
        __syncthreads();
        if (tid < cnt) se[tid] = d_epk[base + tid];
        __syncthreads();
        int k = 0;
        for (; k + 3 < cnt; k += 4) {
            EdgeP e0 = se[k], e1 = se[k + 1], e2 = se[k + 2], e3 = se[k + 3];
            float4 v0 = zb[e0.src * 128];
            float4 v1 = zb[e1.src * 128];
            float4 v2 = zb[e2.src * 128];
            float4 v3 = zb[e3.src * 128];
            acc.x += e0.w * v0.x + e1.w * v1.x + e2.w * v2.x + e3.w * v3.x;
            acc.y += e0.w * v0.y + e1.w * v1.y + e2.w * v2.y + e3.w * v3.y;
            acc.z += e0.w * v0.z + e1.w * v1.z + e2.w * v2.z + e3.w * v3.z;
            acc.w += e0.w * v0.w + e1.w * v1.w + e2.w * v2.w + e3.w * v3.w;
        }
        for (; k < cnt; k++) {
            EdgeP e0 = se[k];
            float4 v0 = zb[e0.src * 128];
            acc.x += e0.w * v0.x; acc.y += e0.w * v0.y;
            acc.z += e0.w * v0.z; acc.w += e0.w * v0.w;
        }
    }
    int o = b * (NN * 128) + n * 128 + q;
    reinterpret_cast<float4*>(outp)[o] = acc;
    __half2 h0 = __floats2half2_rn(acc.x, acc.y);
    __half2 h1 = __floats2half2_rn(acc.z, acc.w);
    uint2 u;
    u.x = *reinterpret_cast<unsigned*>(&h0);
    u.y = *reinterpret_cast<unsigned*>(&h1);
    reinterpret_cast<uint2*>(outh)[o] = u;
}

// ---------------- prop2: smem-staged edges, 4-way MLP f16 gather; writes P2 fp32 ----------------
__global__ __launch_bounds__(256) void prop2_kernel(const __half* __restrict__ zh,
                                                    float* __restrict__ outp) {
    __shared__ EdgeP se[256];
    int n = blockIdx.x;
    int tid = threadIdx.x;
    int b = tid >> 7;
    int q = tid & 127;
    const uint2* zb = reinterpret_cast<const uint2*>(zh) + b * (NN * 128) + q;
    float4 acc = make_float4(0.f, 0.f, 0.f, 0.f);
    int s = d_ptr[n], e = d_ptr[n + 1];
    for (int base = s; base < e; base += 256) {
        int cnt = min(256, e - base);
        __syncthreads();
        if (tid < cnt) se[tid] = d_epk[base + tid];
        __syncthreads();
        int k = 0;
        for (; k + 3 < cnt; k += 4) {
            EdgeP e0 = se[k], e1 = se[k + 1], e2 = se[k + 2], e3 = se[k + 3];
            uint2 r0 = zb[e0.src * 128];
            uint2 r1 = zb[e1.src * 128];
            uint2 r2 = zb[e2.src * 128];
            uint2 r3 = zb[e3.src * 128];
            float2 a0 = __half22float2(*reinterpret_cast<__half2*>(&r0.x));
            float2 a1 = __half22float2(*reinterpret_cast<__half2*>(&r0.y));
            float2 b0 = __half22float2(*reinterpret_cast<__half2*>(&r1.x));
            float2 b1 = __half22float2(*reinterpret_cast<__half2*>(&r1.y));
            float2 c0 = __half22float2(*reinterpret_cast<__half2*>(&r2.x));
            float2 c1 = __half22float2(*reinterpret_cast<__half2*>(&r2.y));
            float2 d0 = __half22float2(*reinterpret_cast<__half2*>(&r3.x));
            float2 d1 = __half22float2(*reinterpret_cast<__half2*>(&r3.y));
            acc.x += e0.w * a0.x + e1.w * b0.x + e2.w * c0.x + e3.w * d0.x;
            acc.y += e0.w * a0.y + e1.w * b0.y + e2.w * c0.y + e3.w * d0.y;
            acc.z += e0.w * a1.x + e1.w * b1.x + e2.w * c1.x + e3.w * d1.x;
            acc.w += e0.w * a1.y + e1.w * b1.y + e2.w * c1.y + e3.w * d1.y;
        }
        for (; k < cnt; k++) {
            EdgeP e0 = se[k];
            uint2 r0 = zb[e0.src * 128];
            float2 a0 = __half22float2(*reinterpret_cast<__half2*>(&r0.x));
            float2 a1 = __half22float2(*reinterpret_cast<__half2*>(&r0.y));
            acc.x += e0.w * a0.x; acc.y += e0.w * a0.y;
            acc.z += e0.w * a1.x; acc.w += e0.w * a1.y;
        }
    }
    reinterpret_cast<float4*>(outp)[b * (NN * 128) + n * 128 + q] = acc;
}

// ================= persistent wmma dense kernel (256 threads, pipelined staging) =================
#define O_BIAS   0         // 1024
#define O_A1H    1024      // 26624 (alias: S_h 144x72; OUT spans A1H+A1L)
#define O_A1L    27648     // 26624
#define O_B1CH   54272     // 96x72 halves = 13824
#define O_B1CL   68096     // 13824
#define O_B1RH   81920     // 32x72 halves = 4608
#define O_B1RL   86528     // 4608
#define O_B2H    91136     // 3x64x72 halves = 27648
#define O_B2L    118784    // 27648
#define O_RES    146432    // 128x68 floats = 34816
#define O_STG    181248    // 8x256 floats = 8192
#define TC_SMEM  189440

#define LDA1 104
#define LDB1 72
#define LDS2 72
#define LDB2 72
#define LDRES 68

__device__ __forceinline__ void split2(float a, float b, unsigned& uh, unsigned& ul) {
    __half h0 = __float2half_rn(a), h1 = __float2half_rn(b);
    __half l0 = __float2half_rn(a - __half2float(h0));
    __half l1 = __float2half_rn(b - __half2float(h1));
    __half2 H = __halves2half2(h0, h1), L = __halves2half2(l0, l1);
    uh = *reinterpret_cast<unsigned*>(&H);
    ul = *reinterpret_cast<unsigned*>(&L);
}

__global__ __launch_bounds__(256, 1) void tc_kernel(
    const float* __restrict__ x,
    const float* __restrict__ cheb_W, const float* __restrict__ cheb_b,
    const float* __restrict__ time_W, const float* __restrict__ time_b,
    const float* __restrict__ res_W,  const float* __restrict__ res_b,
    const float* __restrict__ ln_g,   const float* __restrict__ ln_b,
    float* __restrict__ outg)
{
    extern __shared__ char sm[];
    float* BIAS  = reinterpret_cast<float*>(sm + O_BIAS);
    __half* A1h  = reinterpret_cast<__half*>(sm + O_A1H);
    __half* A1l  = reinterpret_cast<__half*>(sm + O_A1L);
    __half* B1ch = reinterpret_cast<__half*>(sm + O_B1CH);
    __half* B1cl = reinterpret_cast<__half*>(sm + O_B1CL);
    __half* B1rh = reinterpret_cast<__half*>(sm + O_B1RH);
    __half* B1rl = reinterpret_cast<__half*>(sm + O_B1RL);
    __half* B2h  = reinterpret_cast<__half*>(sm + O_B2H);
    __half* B2l  = reinterpret_cast<__half*>(sm + O_B2L);
    __half* Sh   = A1h;
    float* RES   = reinterpret_cast<float*>(sm + O_RES);
    float* STGb  = reinterpret_cast<float*>(sm + O_STG);
    float* OUT   = reinterpret_cast<float*>(sm + O_A1H);

    int tid = threadIdx.x, warp = tid >> 5, lane = tid & 31;

    // ---- one-time weight staging ----
    for (int idx = tid; idx < 96 * 8; idx += 256) {
        int k = idx >> 3, n0 = (idx & 7) * 8;
        unsigned uh[4], ul[4];
#pragma unroll
        for (int i = 0; i < 4; i++) {
            float v[2];
#pragma unroll
            for (int j = 0; j < 2; j++) {
                int n = n0 + 2 * i + j;
                float val;
                if (k < 32)      val = cheb_W[k * 64 + n] - cheb_W[4096 + k * 64 + n];
                else if (k < 64) val = cheb_W[2048 + (k - 32) * 64 + n];
                else             val = 2.f * cheb_W[4096 + (k - 64) * 64 + n];
                v[j] = val;
            }
            split2(v[0], v[1], uh[i], ul[i]);
        }
        *reinterpret_cast<uint4*>(&B1ch[k * LDB1 + n0]) = make_uint4(uh[0], uh[1], uh[2], uh[3]);
        *reinterpret_cast<uint4*>(&B1cl[k * LDB1 + n0]) = make_uint4(ul[0], ul[1], ul[2], ul[3]);
    }
    for (int idx = tid; idx < 32 * 8; idx += 256) {
        int k = idx >> 3, n0 = (idx & 7) * 8;
        unsigned uh[4], ul[4];
#pragma unroll
        for (int i = 0; i < 4; i++) {
            float v0 = res_W[(n0 + 2 * i) * 32 + k];
            float v1 = res_W[(n0 + 2 * i + 1) * 32 + k];
            split2(v0, v1, uh[i], ul[i]);
        }
        *reinterpret_cast<uint4*>(&B1rh[k * LDB1 + n0]) = make_uint4(uh[0], uh[1], uh[2], uh[3]);
        *reinterpret_cast<uint4*>(&B1rl[k * LDB1 + n0]) = make_uint4(ul[0], ul[1], ul[2], ul[3]);
    }
    for (int idx = tid; idx < 3 * 64 * 8; idx += 256) {
        int dt = idx / 512, rem = idx % 512;
        int c = rem >> 3, n0 = (rem & 7) * 8;
        unsigned uh[4], ul[4];
#pragma unroll
        for (int i = 0; i < 4; i++) {
            float v0 = time_W[(n0 + 2 * i) * 192 + c * 3 + dt];
            float v1 = time_W[(n0 + 2 * i + 1) * 192 + c * 3 + dt];
            split2(v0, v1, uh[i], ul[i]);
        }
        *reinterpret_cast<uint4*>(&B2h[dt * 4608 + c * LDB2 + n0]) = make_uint4(uh[0], uh[1], uh[2], uh[3]);
        *reinterpret_cast<uint4*>(&B2l[dt * 4608 + c * LDB2 + n0]) = make_uint4(ul[0], ul[1], ul[2], ul[3]);
    }
    if (tid < 64) {
        BIAS[tid]       = cheb_b[tid];
        BIAS[64 + tid]  = time_b[tid] + res_b[tid];
        BIAS[128 + tid] = ln_g[tid];
        BIAS[192 + tid] = ln_b[tid];
    }
    __syncthreads();

    float* stg = STGb + warp * 256;
    int er = lane >> 1, ec0 = (lane & 1) * 8;
    int sm_ = tid >> 1, shf = tid & 1;     // staging row / half
    int sp = sm_ >> 4, st = sm_ & 15;

    // ---- prefetch registers: 48 floats = this thread's A1 slice for the CURRENT tile ----
    float pf[48];
    {
        int tl = blockIdx.x;
        if (tl < NTILES) {
            size_t poff = (size_t)(tl * 8 + sp) * NODE_FLOATS;
#pragma unroll
            for (int g = 0; g < 6; g++) {
                int k0 = shf * 48 + g * 8;
                const float* src = (k0 < 32) ? x + poff : (k0 < 64 ? d_Tx1 + poff : d_P2 + poff);
                int f0 = k0 & 31;
#pragma unroll
                for (int i = 0; i < 8; i++)
                    pf[g * 8 + i] = src[(f0 + i) * 16 + st];
            }
        }
    }

    for (int tile = blockIdx.x; tile < NTILES; tile += gridDim.x) {
        // ---- write prefetched A1 slice to smem (f16 hi/lo) — no global loads ----
        {
#pragma unroll
            for (int g = 0; g < 6; g++) {
                int k0 = shf * 48 + g * 8;
                unsigned uh[4], ul[4];
#pragma unroll
                for (int i = 0; i < 4; i++)
                    split2(pf[g * 8 + 2 * i], pf[g * 8 + 2 * i + 1], uh[i], ul[i]);
                *reinterpret_cast<uint4*>(&A1h[sm_ * LDA1 + k0]) = make_uint4(uh[0], uh[1], uh[2], uh[3]);
                *reinterpret_cast<uint4*>(&A1l[sm_ * LDA1 + k0]) = make_uint4(ul[0], ul[1], ul[2], ul[3]);
            }
        }
        __syncthreads();

        // ---- GEMM1a: cheb C[128x64] = A[:, 0:96] @ B1c; GEMM1b: res K=32 ----
        wmma::fragment<wmma::accumulator, 16, 16, 16, float> accc[4], accr[4];
#pragma unroll
        for (int nt = 0; nt < 4; nt++) { wmma::fill_fragment(accc[nt], 0.f); wmma::fill_fragment(accr[nt], 0.f); }
#pragma unroll
        for (int kt = 0; kt < 6; kt++) {
            wmma::fragment<wmma::matrix_a, 16, 16, 16, __half, wmma::row_major> ah, al;
            wmma::load_matrix_sync(ah, &A1h[(warp * 16) * LDA1 + kt * 16], LDA1);
            wmma::load_matrix_sync(al, &A1l[(warp * 16) * LDA1 + kt * 16], LDA1);
#pragma unroll
            for (int nt = 0; nt < 4; nt++) {
                wmma::fragment<wmma::matrix_b, 16, 16, 16, __half, wmma::row_major> bh, bl;
                wmma::load_matrix_sync(bh, &B1ch[(kt * 16) * LDB1 + nt * 16], LDB1);
                wmma::load_matrix_sync(bl, &B1cl[(kt * 16) * LDB1 + nt * 16], LDB1);
                wmma::mma_sync(accc[nt], ah, bh, accc[nt]);
                wmma::mma_sync(accc[nt], al, bh, accc[nt]);
                wmma::mma_sync(accc[nt], ah, bl, accc[nt]);
            }
            if (kt < 2) {
#pragma unroll
                for (int nt = 0; nt < 4; nt++) {
                    wmma::fragment<wmma::matrix_b, 16, 16, 16, __half, wmma::row_major> bh, bl;
                    wmma::load_matrix_sync(bh, &B1rh[(kt * 16) * LDB1 + nt * 16], LDB1);
                    wmma::load_matrix_sync(bl, &B1rl[(kt * 16) * LDB1 + nt * 16], LDB1);
                    wmma::mma_sync(accr[nt], ah, bh, accr[nt]);
                    wmma::mma_sync(accr[nt], al, bh, accr[nt]);
                    wmma::mma_sync(accr[nt], ah, bl, accr[nt]);
                }
            }
        }
        __syncthreads();   // A1 reads done; S may overwrite A1 region

        // ---- PREFETCH next tile's A1 slice (completes under epilogues/GEMM2/LN) ----
        {
            int nxt = tile + gridDim.x;
            if (nxt < NTILES) {
                size_t poff = (size_t)(nxt * 8 + sp) * NODE_FLOATS;
#pragma unroll
                for (int g = 0; g < 6; g++) {
                    int k0 = shf * 48 + g * 8;
                    const float* src = (k0 < 32) ? x + poff : (k0 < 64 ? d_Tx1 + poff : d_P2 + poff);
                    int f0 = k0 & 31;
#pragma unroll
                    for (int i = 0; i < 8; i++)
                        pf[g * 8 + i] = src[(f0 + i) * 16 + st];
                }
            }
        }

        // ---- zero S halo rows (0..7 and 136..143), Sh only ----
        for (int i = tid; i < 144; i += 256) {
            int r = i % 144;
            int off = (r < 72) ? r * 16 : 19584 + (r - 72) * 16;
            *reinterpret_cast<uint4*>(reinterpret_cast<char*>(Sh) + off) = make_uint4(0, 0, 0, 0);
        }

        // ---- epilogue 1: cheb -> s f16 (relu+bias, shifted rows); res -> RES ----
#pragma unroll
        for (int nt = 0; nt < 4; nt++) {
            wmma::store_matrix_sync(stg, accc[nt], 16, wmma::mem_row_major);
            __syncwarp();
            int cc = nt * 16 + ec0;
            unsigned u[4];
#pragma unroll
            for (int i = 0; i < 4; i++) {
                float v0 = fmaxf(stg[er * 16 + ec0 + 2 * i]     + BIAS[cc + 2 * i], 0.f);
                float v1 = fmaxf(stg[er * 16 + ec0 + 2 * i + 1] + BIAS[cc + 2 * i + 1], 0.f);
                __half2 H = __floats2half2_rn(v0, v1);
                u[i] = *reinterpret_cast<unsigned*>(&H);
            }
            int sr = 8 * er + 8 + warp;
            *reinterpret_cast<uint4*>(&Sh[sr * LDS2 + cc]) = make_uint4(u[0], u[1], u[2], u[3]);
            __syncwarp();
        }
#pragma unroll
        for (int nt = 0; nt < 4; nt++) {
            wmma::store_matrix_sync(stg, accr[nt], 16, wmma::mem_row_major);
            __syncwarp();
            int cc = nt * 16 + ec0;
            int mr = warp * 16 + er;
            float4 v0, v1;
            v0.x = stg[er * 16 + ec0 + 0] + BIAS[64 + cc + 0];
            v0.y = stg[er * 16 + ec0 + 1] + BIAS[64 + cc + 1];
            v0.z = stg[er * 16 + ec0 + 2] + BIAS[64 + cc + 2];
            v0.w = stg[er * 16 + ec0 + 3] + BIAS[64 + cc + 3];
            v1.x = stg[er * 16 + ec0 + 4] + BIAS[64 + cc + 4];
            v1.y = stg[er * 16 + ec0 + 5] + BIAS[64 + cc + 5];
            v1.z = stg[er * 16 + ec0 + 6] + BIAS[64 + cc + 6];
            v1.w = stg[er * 16 + ec0 + 7] + BIAS[64 + cc + 7];
            *reinterpret_cast<float4*>(&RES[mr * LDRES + cc])     = v0;
            *reinterpret_cast<float4*>(&RES[mr * LDRES + cc + 4]) = v1;
            __syncwarp();
        }
        __syncthreads();

        // ---- GEMM2: temporal conv, 3 row-shifted GEMMs, 2 terms ----
        wmma::fragment<wmma::accumulator, 16, 16, 16, float> acc2[4];
#pragma unroll
        for (int nt = 0; nt < 4; nt++) wmma::fill_fragment(acc2[nt], 0.f);
#pragma unroll
        for (int dt = 0; dt < 3; dt++) {
#pragma unroll
            for (int ct = 0; ct < 4; ct++) {
                wmma::fragment<wmma::matrix_a, 16, 16, 16, __half, wmma::row_major> ah;
                wmma::load_matrix_sync(ah, &Sh[(warp * 16 + dt * 8) * LDS2 + ct * 16], LDS2);
#pragma unroll
                for (int nt = 0; nt < 4; nt++) {
                    wmma::fragment<wmma::matrix_b, 16, 16, 16, __half, wmma::row_major> bh, bl;
                    wmma::load_matrix_sync(bh, &B2h[dt * 4608 + (ct * 16) * LDB2 + nt * 16], LDB2);
                    wmma::load_matrix_sync(bl, &B2l[dt * 4608 + (ct * 16) * LDB2 + nt * 16], LDB2);
                    wmma::mma_sync(acc2[nt], ah, bh, acc2[nt]);
                    wmma::mma_sync(acc2[nt], ah, bl, acc2[nt]);
                }
            }
        }
        __syncthreads();

        // ---- epilogue 2: z = relu(D2 + RES) in place ----
#pragma unroll
        for (int nt = 0; nt < 4; nt++) {
            wmma::store_matrix_sync(stg, acc2[nt], 16, wmma::mem_row_major);
            __syncwarp();
            int m2 = warp * 16 + er;
            int t2 = m2 >> 3, p2 = m2 & 7;
            int mr = p2 * 16 + t2;
            int cc = nt * 16 + ec0;
            float4 a = *reinterpret_cast<float4*>(&RES[mr * LDRES + cc]);
            float4 b = *reinterpret_cast<float4*>(&RES[mr * LDRES + cc + 4]);
            a.x = fmaxf(a.x + stg[er * 16 + ec0 + 0], 0.f);
            a.y = fmaxf(a.y + stg[er * 16 + ec0 + 1], 0.f);
            a.z = fmaxf(a.z + stg[er * 16 + ec0 + 2], 0.f);
            a.w = fmaxf(a.w + stg[er * 16 + ec0 + 3], 0.f);
            b.x = fmaxf(b.x + stg[er * 16 + ec0 + 4], 0.f);
            b.y = fmaxf(b.y + stg[er * 16 + ec0 + 5], 0.f);
            b.z = fmaxf(b.z + stg[er * 16 + ec0 + 6], 0.f);
            b.w = fmaxf(b.w + stg[er * 16 + ec0 + 7], 0.f);
            *reinterpret_cast<float4*>(&RES[mr * LDRES + cc])     = a;
            *reinterpret_cast<float4*>(&RES[mr * LDRES + cc + 4]) = b;
            __syncwarp();
        }
        __syncthreads();

        // ---- LayerNorm per (p,t) row -> OUT smem ----
        if (tid < 128) {
            int p = tid >> 4, t = tid & 15;
            float z[64];
            float s1 = 0.f, s2 = 0.f;
#pragma unroll
            for (int c = 0; c < 64; c++) {
                float v = RES[tid * LDRES + c];
                z[c] = v;
                s1 += v;
                s2 += v * v;
            }
            float mu = s1 * 0.015625f;
            float var = fmaf(-mu, mu, s2 * 0.015625f);
            float rs = rsqrtf(var + 1e-5f);
#pragma unroll
            for (int c = 0; c < 64; c++)
                OUT[p * 1024 + c * 16 + t] = fmaf((z[c] - mu) * rs, BIAS[128 + c], BIAS[192 + c]);
        }
        __syncthreads();

        // ---- coalesced global store ----
        {
            float4* og = reinterpret_cast<float4*>(outg + (size_t)tile * 8192);
            const float4* o4 = reinterpret_cast<const float4*>(OUT);
            for (int i = tid; i < 2048; i += 256) og[i] = o4[i];
        }
        __syncthreads();
    }
}

// ---------------- launch ----------------
extern "C" void kernel_launch(void* const* d_in, const int* in_sizes, int n_in,
                              void* d_out, int out_size) {
    const float* x       = (const float*)d_in[0];
    const int*   edge    = (const int*)  d_in[1];
    const float* cheb_W  = (const float*)d_in[2];
    const float* cheb_b  = (const float*)d_in[3];
    const float* time_W  = (const float*)d_in[4];
    const float* time_b  = (const float*)d_in[5];
    const float* res_W   = (const float*)d_in[6];
    const float* res_b   = (const float*)d_in[7];
    const float* ln_g    = (const float*)d_in[8];
    const float* ln_b    = (const float*)d_in[9];
    float* out = (float*)d_out;

    const int* row = edge;
    const int* col = edge + EE;

    cudaFuncSetAttribute(tc_kernel, cudaFuncAttributeMaxDynamicSharedMemorySize, TC_SMEM);

    float*  Tx1p;  cudaGetSymbolAddress((void**)&Tx1p,  d_Tx1);
    __half* Tx1hp; cudaGetSymbolAddress((void**)&Tx1hp, d_Tx1h);
    float*  P2p;   cudaGetSymbolAddress((void**)&P2p,   d_P2);

    // counts are zero at entry (zero-initialized globals; scan resets them each call)
    count_kernel<<<(EE + 255) / 256, 256>>>(row, col);
    scan_kernel<<<1, 1024>>>();
    fill_kernel<<<(EE + 255) / 256, 256>>>(row, col);

    prop1_kernel<<<NN, 256>>>(x, Tx1p, Tx1hp);
    prop2_kernel<<<NN, 256>>>(Tx1hp, P2p);

    tc_kernel<<<148, 256, TC_SMEM>>>(
        x, cheb_W, cheb_b, time_W, time_b, res_W, res_b, ln_g, ln_b, out);
}

// round 17
// speedup vs baseline: 1.0222x; 1.0222x over previous
#include <cuda_runtime.h>
#include <cuda_fp16.h>
#include <mma.h>
#include <cstdint>
#include <cstddef>

using namespace nvcuda;

#define NN 10000
#define EE 160000
#define PAIRS 20000
#define NODE_FLOATS 512
#define NTILES 2500

struct __align__(8) EdgeP { int src; float w; };

// ---------------- device scratch ----------------
__device__ float  d_Tx1[(size_t)PAIRS * NODE_FLOATS];
__device__ __half d_Tx1h[(size_t)PAIRS * NODE_FLOATS];
__device__ float  d_P2 [(size_t)PAIRS * NODE_FLOATS];
__device__ int   d_degc[NN];     // zero at launch entry (reset by scan_kernel)
__device__ float d_dinv[NN];
__device__ int   d_cnt[NN];      // zero at launch entry (reset by scan_kernel)
__device__ int   d_ptr[NN + 1];
__device__ int   d_wr[NN];
__device__ EdgeP d_epk[EE];

// ---------------- CSR build ----------------
__global__ void count_kernel(const int* __restrict__ row, const int* __restrict__ col) {
    int e = blockIdx.x * blockDim.x + threadIdx.x;
    if (e < EE) {
        atomicAdd(&d_degc[row[e]], 1);
        atomicAdd(&d_cnt[col[e]], 1);
    }
}

// dinv + chunked scan (coalesced d_ptr/d_wr writes) + reset counts for next replay
__global__ void scan_kernel() {
    __shared__ int buf[NN];       // 40KB
    __shared__ int wsum[32];
    __shared__ int carry;
    int tid = threadIdx.x, lane = tid & 31, wid = tid >> 5;
    if (tid == 0) carry = 0;
    for (int i = tid; i < NN; i += 1024) {
        int d = d_degc[i];
        d_dinv[i] = (d > 0) ? rsqrtf((float)d) : 0.f;
        buf[i] = d_cnt[i];
        d_degc[i] = 0;
        d_cnt[i]  = 0;
    }
    __syncthreads();
    for (int base = 0; base < NN; base += 1024) {
        int i = base + tid;
        int v = (i < NN) ? buf[i] : 0;
        int s = v;
#pragma unroll
        for (int off = 1; off < 32; off <<= 1) {
            int t = __shfl_up_sync(0xffffffffu, s, off);
            if (lane >= off) s += t;
        }
        if (lane == 31) wsum[wid] = s;
        __syncthreads();
        if (wid == 0) {
            int ws = wsum[lane];
#pragma unroll
            for (int off = 1; off < 32; off <<= 1) {
                int t = __shfl_up_sync(0xffffffffu, ws, off);
                if (lane >= off) ws += t;
            }
            wsum[lane] = ws;
        }
        __syncthreads();
        int incl = s + ((wid > 0) ? wsum[wid - 1] : 0);
        int c0 = carry;
        if (i < NN) { int ex = c0 + incl - v; d_ptr[i] = ex; d_wr[i] = ex; }
        __syncthreads();
        if (tid == 1023) carry = c0 + incl;
        __syncthreads();
    }
    if (tid == 0) d_ptr[NN] = carry;
}

__global__ void fill_kernel(const int* __restrict__ row, const int* __restrict__ col) {
    int e = blockIdx.x * blockDim.x + threadIdx.x;
    if (e < EE) {
        int r = row[e], c = col[e];
        float wv = -(d_dinv[r] * d_dinv[c]);
        int pos = atomicAdd(&d_wr[c], 1);
        EdgeP ep; ep.src = r; ep.w = wv;
        d_epk[pos] = ep;
    }
}

// ---------------- prop1: smem-staged edges, fp32 gather; writes Tx1 fp32 + f16 ----------------
__global__ __launch_bounds__(256) void prop1_kernel(const float* __restrict__ z,
                                                    float* __restrict__ outp,
                                                    __half* __restrict__ outh) {
    __shared__ EdgeP se[256];
    int n = blockIdx.x;
    int tid = threadIdx.x;
    int b = tid >> 7;
    int q = tid & 127;
    const float4* zb = reinterpret_cast<const float4*>(z) + b * (NN * 128) + q;
    float4 acc = make_float4(0.f, 0.f, 0.f, 0.f);
    int s = d_ptr[n], e = d_ptr[n + 1];
    for (int base = s; base < e; base += 256) {
        int cnt = min(256, e - base);
        __syncthreads();
        if (tid < cnt) se[tid] = d_epk[base + tid];
        __syncthreads();
        int k = 0;
        for (; k + 1 < cnt; k += 2) {
            EdgeP e0 = se[k], e1 = se[k + 1];
            float4 v0 = zb[e0.src * 128];
            float4 v1 = zb[e1.src * 128];
            acc.x += e0.w * v0.x + e1.w * v1.x;
            acc.y += e0.w * v0.y + e1.w * v1.y;
            acc.z += e0.w * v0.z + e1.w * v1.z;
            acc.w += e0.w * v0.w + e1.w * v1.w;
        }
        if (k < cnt) {
            EdgeP e0 = se[k];
            float4 v0 = zb[e0.src * 128];
            acc.x += e0.w * v0.x; acc.y += e0.w * v0.y;
            acc.z += e0.w * v0.z; acc.w += e0.w * v0.w;
        }
    }
    int o = b * (NN * 128) + n * 128 + q;
    reinterpret_cast<float4*>(outp)[o] = acc;
    __half2 h0 = __floats2half2_rn(acc.x, acc.y);
    __half2 h1 = __floats2half2_rn(acc.z, acc.w);
    uint2 u;
    u.x = *reinterpret_cast<unsigned*>(&h0);
    u.y = *reinterpret_cast<unsigned*>(&h1);
    reinterpret_cast<uint2*>(outh)[o] = u;
}

// ---------------- prop2: smem-staged edges, f16 gather of Tx1h; writes P2 fp32 ----------------
__global__ __launch_bounds__(256) void prop2_kernel(const __half* __restrict__ zh,
                                                    float* __restrict__ outp) {
    __shared__ EdgeP se[256];
    int n = blockIdx.x;
    int tid = threadIdx.x;
    int b = tid >> 7;
    int q = tid & 127;
    const uint2* zb = reinterpret_cast<const uint2*>(zh) + b * (NN * 128) + q;
    float4 acc = make_float4(0.f, 0.f, 0.f, 0.f);
    int s = d_ptr[n], e = d_ptr[n + 1];
    for (int base = s; base < e; base += 256) {
        int cnt = min(256, e - base);
        __syncthreads();
        if (tid < cnt) se[tid] = d_epk[base + tid];
        __syncthreads();
        int k = 0;
        for (; k + 1 < cnt; k += 2) {
            EdgeP e0 = se[k], e1 = se[k + 1];
            uint2 r0 = zb[e0.src * 128];
            uint2 r1 = zb[e1.src * 128];
            float2 a0 = __half22float2(*reinterpret_cast<__half2*>(&r0.x));
            float2 a1 = __half22float2(*reinterpret_cast<__half2*>(&r0.y));
            float2 b0 = __half22float2(*reinterpret_cast<__half2*>(&r1.x));
            float2 b1 = __half22float2(*reinterpret_cast<__half2*>(&r1.y));
            acc.x += e0.w * a0.x + e1.w * b0.x;
            acc.y += e0.w * a0.y + e1.w * b0.y;
            acc.z += e0.w * a1.x + e1.w * b1.x;
            acc.w += e0.w * a1.y + e1.w * b1.y;
        }
        if (k < cnt) {
            EdgeP e0 = se[k];
            uint2 r0 = zb[e0.src * 128];
            float2 a0 = __half22float2(*reinterpret_cast<__half2*>(&r0.x));
            float2 a1 = __half22float2(*reinterpret_cast<__half2*>(&r0.y));
            acc.x += e0.w * a0.x; acc.y += e0.w * a0.y;
            acc.z += e0.w * a1.x; acc.w += e0.w * a1.y;
        }
    }
    reinterpret_cast<float4*>(outp)[b * (NN * 128) + n * 128 + q] = acc;
}

// ================= persistent wmma dense kernel =================
// A1l now only 128 x 32 (k<32 lo parts); al MMAs only for kt<2
#define O_BIAS   0         // 1024
#define O_A1H    1024      // 26624 (alias: S_h 144x72; OUT spans A1H+A1L)
#define O_A1L    27648     // 128x32 halves = 8192
#define O_B1CH   35840     // 96x72 halves = 13824
#define O_B1CL   49664     // 13824
#define O_B1RH   63488     // 32x72 halves = 4608
#define O_B1RL   68096     // 4608
#define O_B2H    72704     // 3x64x72 halves = 27648
#define O_B2L    100352    // 27648
#define O_RES    128000    // 128x68 floats = 34816
#define O_STG    162816    // 8x256 floats = 8192
#define TC_SMEM  171008

#define LDA1  104
#define LDA1L 32
#define LDB1  72
#define LDS2  72
#define LDB2  72
#define LDRES 68

__device__ __forceinline__ void split2(float a, float b, unsigned& uh, unsigned& ul) {
    __half h0 = __float2half_rn(a), h1 = __float2half_rn(b);
    __half l0 = __float2half_rn(a - __half2float(h0));
    __half l1 = __float2half_rn(b - __half2float(h1));
    __half2 H = __halves2half2(h0, h1), L = __halves2half2(l0, l1);
    uh = *reinterpret_cast<unsigned*>(&H);
    ul = *reinterpret_cast<unsigned*>(&L);
}

__global__ __launch_bounds__(256, 1) void tc_kernel(
    const float* __restrict__ x,
    const float* __restrict__ cheb_W, const float* __restrict__ cheb_b,
    const float* __restrict__ time_W, const float* __restrict__ time_b,
    const float* __restrict__ res_W,  const float* __restrict__ res_b,
    const float* __restrict__ ln_g,   const float* __restrict__ ln_b,
    float* __restrict__ outg)
{
    extern __shared__ char sm[];
    float* BIAS  = reinterpret_cast<float*>(sm + O_BIAS);
    __half* A1h  = reinterpret_cast<__half*>(sm + O_A1H);
    __half* A1l  = reinterpret_cast<__half*>(sm + O_A1L);
    __half* B1ch = reinterpret_cast<__half*>(sm + O_B1CH);
    __half* B1cl = reinterpret_cast<__half*>(sm + O_B1CL);
    __half* B1rh = reinterpret_cast<__half*>(sm + O_B1RH);
    __half* B1rl = reinterpret_cast<__half*>(sm + O_B1RL);
    __half* B2h  = reinterpret_cast<__half*>(sm + O_B2H);
    __half* B2l  = reinterpret_cast<__half*>(sm + O_B2L);
    __half* Sh   = A1h;
    float* RES   = reinterpret_cast<float*>(sm + O_RES);
    float* STGb  = reinterpret_cast<float*>(sm + O_STG);
    float* OUT   = reinterpret_cast<float*>(sm + O_A1H);

    int tid = threadIdx.x, warp = tid >> 5, lane = tid & 31;

    // ---- one-time weight staging ----
    for (int idx = tid; idx < 96 * 8; idx += 256) {
        int k = idx >> 3, n0 = (idx & 7) * 8;
        unsigned uh[4], ul[4];
#pragma unroll
        for (int i = 0; i < 4; i++) {
            float v[2];
#pragma unroll
            for (int j = 0; j < 2; j++) {
                int n = n0 + 2 * i + j;
                float val;
                if (k < 32)      val = cheb_W[k * 64 + n] - cheb_W[4096 + k * 64 + n];
                else if (k < 64) val = cheb_W[2048 + (k - 32) * 64 + n];
                else             val = 2.f * cheb_W[4096 + (k - 64) * 64 + n];
                v[j] = val;
            }
            split2(v[0], v[1], uh[i], ul[i]);
        }
        *reinterpret_cast<uint4*>(&B1ch[k * LDB1 + n0]) = make_uint4(uh[0], uh[1], uh[2], uh[3]);
        *reinterpret_cast<uint4*>(&B1cl[k * LDB1 + n0]) = make_uint4(ul[0], ul[1], ul[2], ul[3]);
    }
    for (int idx = tid; idx < 32 * 8; idx += 256) {
        int k = idx >> 3, n0 = (idx & 7) * 8;
        unsigned uh[4], ul[4];
#pragma unroll
        for (int i = 0; i < 4; i++) {
            float v0 = res_W[(n0 + 2 * i) * 32 + k];
            float v1 = res_W[(n0 + 2 * i + 1) * 32 + k];
            split2(v0, v1, uh[i], ul[i]);
        }
        *reinterpret_cast<uint4*>(&B1rh[k * LDB1 + n0]) = make_uint4(uh[0], uh[1], uh[2], uh[3]);
        *reinterpret_cast<uint4*>(&B1rl[k * LDB1 + n0]) = make_uint4(ul[0], ul[1], ul[2], ul[3]);
    }
    for (int idx = tid; idx < 3 * 64 * 8; idx += 256) {
        int dt = idx / 512, rem = idx % 512;
        int c = rem >> 3, n0 = (rem & 7) * 8;
        unsigned uh[4], ul[4];
#pragma unroll
        for (int i = 0; i < 4; i++) {
            float v0 = time_W[(n0 + 2 * i) * 192 + c * 3 + dt];
            float v1 = time_W[(n0 + 2 * i + 1) * 192 + c * 3 + dt];
            split2(v0, v1, uh[i], ul[i]);
        }
        *reinterpret_cast<uint4*>(&B2h[dt * 4608 + c * LDB2 + n0]) = make_uint4(uh[0], uh[1], uh[2], uh[3]);
        *reinterpret_cast<uint4*>(&B2l[dt * 4608 + c * LDB2 + n0]) = make_uint4(ul[0], ul[1], ul[2], ul[3]);
    }
    if (tid < 64) {
        BIAS[tid]       = cheb_b[tid];
        BIAS[64 + tid]  = time_b[tid] + res_b[tid];
        BIAS[128 + tid] = ln_g[tid];
        BIAS[192 + tid] = ln_b[tid];
    }
    __syncthreads();

    float* stg = STGb + warp * 256;
    int er = lane >> 1, ec0 = (lane & 1) * 8;
    int sm_ = tid >> 1, shf = tid & 1;     // staging row / half
    int sp = sm_ >> 4, st = sm_ & 15;

    // ---- prefetch registers: 48 floats = this thread's A1 slice for the CURRENT tile ----
    float pf[48];
    {
        int tl = blockIdx.x;
        if (tl < NTILES) {
            size_t poff = (size_t)(tl * 8 + sp) * NODE_FLOATS;
#pragma unroll
            for (int g = 0; g < 6; g++) {
                int k0 = shf * 48 + g * 8;
                const float* src = (k0 < 32) ? x + poff : (k0 < 64 ? d_Tx1 + poff : d_P2 + poff);
                int f0 = k0 & 31;
#pragma unroll
                for (int i = 0; i < 8; i++)
                    pf[g * 8 + i] = src[(f0 + i) * 16 + st];
            }
        }
    }

    for (int tile = blockIdx.x; tile < NTILES; tile += gridDim.x) {
        // ---- write prefetched A1 slice to smem; lo parts only for k<32 ----
        {
#pragma unroll
            for (int g = 0; g < 6; g++) {
                int k0 = shf * 48 + g * 8;
                if (k0 < 32) {
                    unsigned uh[4], ul[4];
#pragma unroll
                    for (int i = 0; i < 4; i++)
                        split2(pf[g * 8 + 2 * i], pf[g * 8 + 2 * i + 1], uh[i], ul[i]);
                    *reinterpret_cast<uint4*>(&A1h[sm_ * LDA1 + k0])  = make_uint4(uh[0], uh[1], uh[2], uh[3]);
                    *reinterpret_cast<uint4*>(&A1l[sm_ * LDA1L + k0]) = make_uint4(ul[0], ul[1], ul[2], ul[3]);
                } else {
                    unsigned uh[4];
#pragma unroll
                    for (int i = 0; i < 4; i++) {
                        __half2 H = __floats2half2_rn(pf[g * 8 + 2 * i], pf[g * 8 + 2 * i + 1]);
                        uh[i] = *reinterpret_cast<unsigned*>(&H);
                    }
                    *reinterpret_cast<uint4*>(&A1h[sm_ * LDA1 + k0]) = make_uint4(uh[0], uh[1], uh[2], uh[3]);
                }
            }
        }
        __syncthreads();

        // ---- GEMM1a: cheb (K=96, al term only kt<2); GEMM1b: res K=32 ----
        wmma::fragment<wmma::accumulator, 16, 16, 16, float> accc[4], accr[4];
#pragma unroll
        for (int nt = 0; nt < 4; nt++) { wmma::fill_fragment(accc[nt], 0.f); wmma::fill_fragment(accr[nt], 0.f); }
#pragma unroll
        for (int kt = 0; kt < 6; kt++) {
            wmma::fragment<wmma::matrix_a, 16, 16, 16, __half, wmma::row_major> ah, al;
            wmma::load_matrix_sync(ah, &A1h[(warp * 16) * LDA1 + kt * 16], LDA1);
            if (kt < 2)
                wmma::load_matrix_sync(al, &A1l[(warp * 16) * LDA1L + kt * 16], LDA1L);
#pragma unroll
            for (int nt = 0; nt < 4; nt++) {
                wmma::fragment<wmma::matrix_b, 16, 16, 16, __half, wmma::row_major> bh, bl;
                wmma::load_matrix_sync(bh, &B1ch[(kt * 16) * LDB1 + nt * 16], LDB1);
                wmma::load_matrix_sync(bl, &B1cl[(kt * 16) * LDB1 + nt * 16], LDB1);
                wmma::mma_sync(accc[nt], ah, bh, accc[nt]);
                wmma::mma_sync(accc[nt], ah, bl, accc[nt]);
                if (kt < 2) wmma::mma_sync(accc[nt], al, bh, accc[nt]);
            }
            if (kt < 2) {
#pragma unroll
                for (int nt = 0; nt < 4; nt++) {
                    wmma::fragment<wmma::matrix_b, 16, 16, 16, __half, wmma::row_major> bh, bl;
                    wmma::load_matrix_sync(bh, &B1rh[(kt * 16) * LDB1 + nt * 16], LDB1);
                    wmma::load_matrix_sync(bl, &B1rl[(kt * 16) * LDB1 + nt * 16], LDB1);
                    wmma::mma_sync(accr[nt], ah, bh, accr[nt]);
                    wmma::mma_sync(accr[nt], al, bh, accr[nt]);
                    wmma::mma_sync(accr[nt], ah, bl, accr[nt]);
                }
            }
        }
        __syncthreads();   // A1 reads done; S may overwrite A1 region

        // ---- PREFETCH next tile's A1 slice ----
        {
            int nxt = tile + gridDim.x;
            if (nxt < NTILES) {
                size_t poff = (size_t)(nxt * 8 + sp) * NODE_FLOATS;
#pragma unroll
                for (int g = 0; g < 6; g++) {
                    int k0 = shf * 48 + g * 8;
                    const float* src = (k0 < 32) ? x + poff : (k0 < 64 ? d_Tx1 + poff : d_P2 + poff);
                    int f0 = k0 & 31;
#pragma unroll
                    for (int i = 0; i < 8; i++)
                        pf[g * 8 + i] = src[(f0 + i) * 16 + st];
                }
            }
        }

        // ---- zero S halo rows (0..7 and 136..143), Sh only ----
        for (int i = tid; i < 144; i += 256) {
            int r = i % 144;
            int off = (r < 72) ? r * 16 : 19584 + (r - 72) * 16;
            *reinterpret_cast<uint4*>(reinterpret_cast<char*>(Sh) + off) = make_uint4(0, 0, 0, 0);
        }

        // ---- epilogue 1: cheb -> s f16 (relu+bias, shifted rows); res -> RES ----
#pragma unroll
        for (int nt = 0; nt < 4; nt++) {
            wmma::store_matrix_sync(stg, accc[nt], 16, wmma::mem_row_major);
            __syncwarp();
            int cc = nt * 16 + ec0;
            unsigned u[4];
#pragma unroll
            for (int i = 0; i < 4; i++) {
                float v0 = fmaxf(stg[er * 16 + ec0 + 2 * i]     + BIAS[cc + 2 * i], 0.f);
                float v1 = fmaxf(stg[er * 16 + ec0 + 2 * i + 1] + BIAS[cc + 2 * i + 1], 0.f);
                __half2 H = __floats2half2_rn(v0, v1);
                u[i] = *reinterpret_cast<unsigned*>(&H);
            }
            int sr = 8 * er + 8 + warp;
            *reinterpret_cast<uint4*>(&Sh[sr * LDS2 + cc]) = make_uint4(u[0], u[1], u[2], u[3]);
            __syncwarp();
        }
#pragma unroll
        for (int nt = 0; nt < 4; nt++) {
            wmma::store_matrix_sync(stg, accr[nt], 16, wmma::mem_row_major);
            __syncwarp();
            int cc = nt * 16 + ec0;
            int mr = warp * 16 + er;
            float4 v0, v1;
            v0.x = stg[er * 16 + ec0 + 0] + BIAS[64 + cc + 0];
            v0.y = stg[er * 16 + ec0 + 1] + BIAS[64 + cc + 1];
            v0.z = stg[er * 16 + ec0 + 2] + BIAS[64 + cc + 2];
            v0.w = stg[er * 16 + ec0 + 3] + BIAS[64 + cc + 3];
            v1.x = stg[er * 16 + ec0 + 4] + BIAS[64 + cc + 4];
            v1.y = stg[er * 16 + ec0 + 5] + BIAS[64 + cc + 5];
            v1.z = stg[er * 16 + ec0 + 6] + BIAS[64 + cc + 6];
            v1.w = stg[er * 16 + ec0 + 7] + BIAS[64 + cc + 7];
            *reinterpret_cast<float4*>(&RES[mr * LDRES + cc])     = v0;
            *reinterpret_cast<float4*>(&RES[mr * LDRES + cc + 4]) = v1;
            __syncwarp();
        }
        __syncthreads();

        // ---- GEMM2: temporal conv, 3 row-shifted GEMMs, 2 terms ----
        wmma::fragment<wmma::accumulator, 16, 16, 16, float> acc2[4];
#pragma unroll
        for (int nt = 0; nt < 4; nt++) wmma::fill_fragment(acc2[nt], 0.f);
#pragma unroll
        for (int dt = 0; dt < 3; dt++) {
#pragma unroll
            for (int ct = 0; ct < 4; ct++) {
                wmma::fragment<wmma::matrix_a, 16, 16, 16, __half, wmma::row_major> ah;
                wmma::load_matrix_sync(ah, &Sh[(warp * 16 + dt * 8) * LDS2 + ct * 16], LDS2);
#pragma unroll
                for (int nt = 0; nt < 4; nt++) {
                    wmma::fragment<wmma::matrix_b, 16, 16, 16, __half, wmma::row_major> bh, bl;
                    wmma::load_matrix_sync(bh, &B2h[dt * 4608 + (ct * 16) * LDB2 + nt * 16], LDB2);
                    wmma::load_matrix_sync(bl, &B2l[dt * 4608 + (ct * 16) * LDB2 + nt * 16], LDB2);
                    wmma::mma_sync(acc2[nt], ah, bh, acc2[nt]);
                    wmma::mma_sync(acc2[nt], ah, bl, acc2[nt]);
                }
            }
        }
        __syncthreads();

        // ---- epilogue 2: z = relu(D2 + RES) in place ----
#pragma unroll
        for (int nt = 0; nt < 4; nt++) {
            wmma::store_matrix_sync(stg, acc2[nt], 16, wmma::mem_row_major);
            __syncwarp();
            int m2 = warp * 16 + er;
            int t2 = m2 >> 3, p2 = m2 & 7;
            int mr = p2 * 16 + t2;
            int cc = nt * 16 + ec0;
            float4 a = *reinterpret_cast<float4*>(&RES[mr * LDRES + cc]);
            float4 b = *reinterpret_cast<float4*>(&RES[mr * LDRES + cc + 4]);
            a.x = fmaxf(a.x + stg[er * 16 + ec0 + 0], 0.f);
            a.y = fmaxf(a.y + stg[er * 16 + ec0 + 1], 0.f);
            a.z = fmaxf(a.z + stg[er * 16 + ec0 + 2], 0.f);
            a.w = fmaxf(a.w + stg[er * 16 + ec0 + 3], 0.f);
            b.x = fmaxf(b.x + stg[er * 16 + ec0 + 4], 0.f);
            b.y = fmaxf(b.y + stg[er * 16 + ec0 + 5], 0.f);
            b.z = fmaxf(b.z + stg[er * 16 + ec0 + 6], 0.f);
            b.w = fmaxf(b.w + stg[er * 16 + ec0 + 7], 0.f);
            *reinterpret_cast<float4*>(&RES[mr * LDRES + cc])     = a;
            *reinterpret_cast<float4*>(&RES[mr * LDRES + cc + 4]) = b;
            __syncwarp();
        }
        __syncthreads();

        // ---- LayerNorm per (p,t) row -> OUT smem ----
        if (tid < 128) {
            int p = tid >> 4, t = tid & 15;
            float z[64];
            float s1 = 0.f, s2 = 0.f;
#pragma unroll
            for (int c = 0; c < 64; c++) {
                float v = RES[tid * LDRES + c];
                z[c] = v;
                s1 += v;
                s2 += v * v;
            }
            float mu = s1 * 0.015625f;
            float var = fmaf(-mu, mu, s2 * 0.015625f);
            float rs = rsqrtf(var + 1e-5f);
#pragma unroll
            for (int c = 0; c < 64; c++)
                OUT[p * 1024 + c * 16 + t] = fmaf((z[c] - mu) * rs, BIAS[128 + c], BIAS[192 + c]);
        }
        __syncthreads();

        // ---- coalesced global store ----
        {
            float4* og = reinterpret_cast<float4*>(outg + (size_t)tile * 8192);
            const float4* o4 = reinterpret_cast<const float4*>(OUT);
            for (int i = tid; i < 2048; i += 256) og[i] = o4[i];
        }
        __syncthreads();
    }
}

// ---------------- launch ----------------
extern "C" void kernel_launch(void* const* d_in, const int* in_sizes, int n_in,
                              void* d_out, int out_size) {
    const float* x       = (const float*)d_in[0];
    const int*   edge    = (const int*)  d_in[1];
    const float* cheb_W  = (const float*)d_in[2];
    const float* cheb_b  = (const float*)d_in[3];
    const float* time_W  = (const float*)d_in[4];
    const float* time_b  = (const float*)d_in[5];
    const float* res_W   = (const float*)d_in[6];
    const float* res_b   = (const float*)d_in[7];
    const float* ln_g    = (const float*)d_in[8];
    const float* ln_b    = (const float*)d_in[9];
    float* out = (float*)d_out;

    const int* row = edge;
    const int* col = edge + EE;

    cudaFuncSetAttribute(tc_kernel, cudaFuncAttributeMaxDynamicSharedMemorySize, TC_SMEM);

    float*  Tx1p;  cudaGetSymbolAddress((void**)&Tx1p,  d_Tx1);
    __half* Tx1hp; cudaGetSymbolAddress((void**)&Tx1hp, d_Tx1h);
    float*  P2p;   cudaGetSymbolAddress((void**)&P2p,   d_P2);

    // counts are zero at entry (zero-initialized globals; scan resets them each call)
    count_kernel<<<(EE + 255) / 256, 256>>>(row, col);
    scan_kernel<<<1, 1024>>>();
    fill_kernel<<<(EE + 255) / 256, 256>>>(row, col);

    prop1_kernel<<<NN, 256>>>(x, Tx1p, Tx1hp);
    prop2_kernel<<<NN, 256>>>(Tx1hp, P2p);

    tc_kernel<<<148, 256, TC_SMEM>>>(
        x, cheb_W, cheb_b, time_W, time_b, res_W, res_b, ln_g, ln_b, out);
}